// round 13
// baseline (speedup 1.0000x reference)
#include <cuda_runtime.h>
#include <cuda_bf16.h>
#include <cstdint>

// FastVCompressor v6.1: FP8 (e4m3) MMA screening (m16n8k32) + exact fp32 rescore.
// vs v6: fix cvt.e4m3x2 destination type (.b16, not .b32) — only change.
//   keys   [4,4096,1024] f32 = d_in[0]
//   values [4,4096,1024] f32 = d_in[1]
//   codebook [256,1024]  f32 = d_in[2]
//   out = keys_c ++ values_c (32M floats)

#define H      1024
#define CODES  256
#define MROWS  64          // rows per CTA
#define NKC    32          // k32 chunks
#define BUFB   12288       // one chunk of e4m3 codebook: 256 codes * 48B slot (32B data)
#define NCAND  32
#define MARGIN 40.0f

// ---- smem layout ----
#define SO_IDX    0                      // 64 ints: final winner per row
#define SO_CNT    256                    // 64 ints: candidate counts
#define SO_RMIN   512                    // 64 floats: screened min per row
#define SO_CSQ    768                    // 256 floats
#define SO_WVAL   1792                   // 64*8 floats: per-warp row mins
#define SO_CAND   3840                   // 64*32 ints = 8192
#define SO_CBUF   12032                  // 2*BUFB = 24576 (128B aligned)
#define SO_XS     36608                  // Xs[2][64][36] f32 = 18432
#define XS_HALF   2304                   // 64*36 floats
#define XS_STRIDE 36
#define SMEM_TOTAL 55040

__device__ float g_csq[CODES];
__device__ __align__(128) unsigned char g_bsplit[NKC * BUFB];   // 384 KB (L2-resident)

// ---------------------------------------------------------------- helpers
static __device__ __forceinline__ uint32_t smem_u32(const void* p) {
    uint32_t a;
    asm("{ .reg .u64 t; cvta.to.shared.u64 t, %1; cvt.u32.u64 %0, t; }"
        : "=r"(a) : "l"(p));
    return a;
}

#define CPA16(dst, src) \
    asm volatile("cp.async.cg.shared.global [%0], [%1], 16;" \
                 :: "r"(dst), "l"(src) : "memory")
#define CPA_COMMIT() asm volatile("cp.async.commit_group;" ::: "memory")
#define CPA_WAIT0()  asm volatile("cp.async.wait_group 0;" ::: "memory")

#define LDSM4(r0, r1, r2, r3, addr)                                             \
    asm volatile("ldmatrix.sync.aligned.m8n8.x4.shared.b16 {%0,%1,%2,%3}, [%4];" \
        : "=r"(r0), "=r"(r1), "=r"(r2), "=r"(r3) : "r"(addr))

// e4m3 MMA: D[16x8] += A[16x32] * B[32x8]
#define MMA8(c, a0, a1, a2, a3, b0, b1)                                         \
    asm volatile("mma.sync.aligned.m16n8k32.row.col.f32.e4m3.e4m3.f32 "         \
        "{%0,%1,%2,%3}, {%4,%5,%6,%7}, {%8,%9}, {%0,%1,%2,%3};"                 \
        : "+f"((c)[0]), "+f"((c)[1]), "+f"((c)[2]), "+f"((c)[3])                \
        : "r"(a0), "r"(a1), "r"(a2), "r"(a3), "r"(b0), "r"(b1))

// float4 -> 4 packed e4m3 bytes [x|y|z|w] (cvt dst is .b16!)
static __device__ __forceinline__ uint32_t cvt4_e4m3(float4 v) {
    uint16_t lo, hi;
    asm("cvt.rn.satfinite.e4m3x2.f32 %0, %1, %2;" : "=h"(lo) : "f"(v.y), "f"(v.x));
    asm("cvt.rn.satfinite.e4m3x2.f32 %0, %1, %2;" : "=h"(hi) : "f"(v.w), "f"(v.z));
    return (uint32_t)lo | ((uint32_t)hi << 16);
}

// ---------------------------------------------------------------- prep: c_sq
__global__ void csq_kernel(const float* __restrict__ cb) {
    const int c = blockIdx.x;
    const float4 v = ((const float4*)(cb + (size_t)c * H))[threadIdx.x];
    float s = v.x * v.x + v.y * v.y + v.z * v.z + v.w * v.w;
    #pragma unroll
    for (int o = 16; o; o >>= 1) s += __shfl_xor_sync(0xffffffffu, s, o);
    __shared__ float ws[8];
    if ((threadIdx.x & 31) == 0) ws[threadIdx.x >> 5] = s;
    __syncthreads();
    if (threadIdx.x == 0) {
        float t = 0.f;
        #pragma unroll
        for (int i = 0; i < 8; ++i) t += ws[i];
        g_csq[c] = t;
    }
}

// ------------------------------------------- prep: codebook e4m3, 48B row slots
__global__ void bprep_kernel(const float* __restrict__ cb) {
    const int code = blockIdx.x;
    const float4 v = ((const float4*)(cb + (size_t)code * H))[threadIdx.x];
    const uint32_t p = cvt4_e4m3(v);           // k = tid*4 .. tid*4+3
    const int k0 = threadIdx.x * 4;
    *(uint32_t*)(g_bsplit + (size_t)(k0 >> 5) * BUFB + code * 48 + (k0 & 31)) = p;
}

// ---------------------------------------------------------------- main VQ
__global__ __launch_bounds__(256, 2) void vq_kernel(
    const float* __restrict__ keys, const float* __restrict__ values,
    const float* __restrict__ cb, float* __restrict__ out)
{
    extern __shared__ char smem[];
    const uint32_t sb = smem_u32(smem);
    const int tid = threadIdx.x, lane = tid & 31, nw = tid >> 5;
    const int bid = blockIdx.x;

    const float* src = (bid < 256) ? keys   + (size_t)bid * MROWS * H
                                   : values + (size_t)(bid - 256) * MROWS * H;

    // X staging: chunk = 64 rows x 32 floats; thread covers slots tid, tid+256
    const int xrow0 = tid >> 3, xpos0 = tid & 7;            // slot tid
    const int xrow1 = (tid + 256) >> 3, xpos1 = tid & 7;    // slot tid+256
    const uint32_t xs_off0 = (uint32_t)(xrow0 * XS_STRIDE + xpos0 * 4) * 4u;
    const uint32_t xs_off1 = (uint32_t)(xrow1 * XS_STRIDE + xpos1 * 4) * 4u;

    // prologue: chunk 0 (B: 3x16B, X: 2x16B per thread) via cp.async
    #pragma unroll
    for (int j = 0; j < 3; ++j) {
        const uint32_t o = (uint32_t)(tid + 256 * j) * 16u;
        CPA16(sb + SO_CBUF + o, g_bsplit + o);
    }
    CPA16(sb + SO_XS + xs_off0, src + (size_t)xrow0 * H + xpos0 * 4);
    CPA16(sb + SO_XS + xs_off1, src + (size_t)xrow1 * H + xpos1 * 4);
    CPA_COMMIT();

    float acc[4][4][4];
    #pragma unroll
    for (int a = 0; a < 4; ++a)
        #pragma unroll
        for (int b = 0; b < 4; ++b)
            #pragma unroll
            for (int c = 0; c < 4; ++c) acc[a][b][c] = 0.f;

    const uint32_t laneoff = (uint32_t)nw * 1536u
        + (uint32_t)((lane & 7) + ((lane >> 4) << 3)) * 48u
        + (uint32_t)((lane >> 3) & 1) * 16u;
    const int r0 = lane >> 2, c0 = (lane & 3) * 2;
    const int q4 = (lane & 3) * 4;            // A-fragment k quad

    for (int kc = 0; kc < NKC; ++kc) {
        const int b = kc & 1;
        CPA_WAIT0();
        __syncthreads();

        if (kc + 1 < NKC) {  // prefetch chunk kc+1 -> buf b^1
            const unsigned char* sg = g_bsplit + (size_t)(kc + 1) * BUFB;
            const uint32_t dstb = sb + SO_CBUF + (uint32_t)(b ^ 1) * BUFB;
            #pragma unroll
            for (int j = 0; j < 3; ++j) {
                const uint32_t o = (uint32_t)(tid + 256 * j) * 16u;
                CPA16(dstb + o, sg + o);
            }
            const uint32_t xd = sb + SO_XS + (uint32_t)(b ^ 1) * (XS_HALF * 4);
            CPA16(xd + xs_off0, src + (size_t)xrow0 * H + (kc + 1) * 32 + xpos0 * 4);
            CPA16(xd + xs_off1, src + (size_t)xrow1 * H + (kc + 1) * 32 + xpos1 * 4);
            CPA_COMMIT();
        }

        // B fragments (e4m3 rows viewed as b16 pairs -> standard ldmatrix)
        const uint32_t bb = sb + SO_CBUF + (uint32_t)b * BUFB;
        uint32_t b0, b1, b2, b3, b4, b5, b6, b7;
        LDSM4(b0, b1, b2, b3, bb + 0 * 768 + laneoff);
        LDSM4(b4, b5, b6, b7, bb + 1 * 768 + laneoff);

        // A fragments: fp32 -> e4m3 in registers
        uint32_t af[16];
        const float* xbuf = (const float*)(smem + SO_XS) + b * XS_HALF;
        #pragma unroll
        for (int mt = 0; mt < 4; ++mt) {
            const int ra = mt * 16 + r0, rb = ra + 8;
            af[mt*4+0] = cvt4_e4m3(*(const float4*)&xbuf[ra * XS_STRIDE + q4]);
            af[mt*4+1] = cvt4_e4m3(*(const float4*)&xbuf[rb * XS_STRIDE + q4]);
            af[mt*4+2] = cvt4_e4m3(*(const float4*)&xbuf[ra * XS_STRIDE + q4 + 16]);
            af[mt*4+3] = cvt4_e4m3(*(const float4*)&xbuf[rb * XS_STRIDE + q4 + 16]);
        }

        #pragma unroll
        for (int mt = 0; mt < 4; ++mt) {
            MMA8(acc[mt][0], af[mt*4+0], af[mt*4+1], af[mt*4+2], af[mt*4+3], b0, b1);
            MMA8(acc[mt][1], af[mt*4+0], af[mt*4+1], af[mt*4+2], af[mt*4+3], b2, b3);
            MMA8(acc[mt][2], af[mt*4+0], af[mt*4+1], af[mt*4+2], af[mt*4+3], b4, b5);
            MMA8(acc[mt][3], af[mt*4+0], af[mt*4+1], af[mt*4+2], af[mt*4+3], b6, b7);
        }
    }

    // ---------------- epilogue: screen -> candidates -> exact rescore ------
    float* csq_s  = (float*)(smem + SO_CSQ);
    float* wval   = (float*)(smem + SO_WVAL);
    float* rmin   = (float*)(smem + SO_RMIN);
    int*   cnt    = (int*)(smem + SO_CNT);
    int*   cand   = (int*)(smem + SO_CAND);
    int*   idxs   = (int*)(smem + SO_IDX);

    __syncthreads();
    csq_s[tid] = g_csq[tid];
    if (tid < MROWS) cnt[tid] = 0;
    __syncthreads();

    // pass 1: per-warp min of screened distance per row
    #pragma unroll
    for (int mt = 0; mt < 4; ++mt)
        #pragma unroll
        for (int h = 0; h < 2; ++h) {
            const int row = mt * 16 + r0 + h * 8;
            float bv = 3.4e38f;
            #pragma unroll
            for (int nt = 0; nt < 4; ++nt) {
                const int col = nw * 32 + nt * 8 + c0;
                const float d0 = csq_s[col]     - 2.0f * acc[mt][nt][2*h];
                const float d1 = csq_s[col + 1] - 2.0f * acc[mt][nt][2*h+1];
                bv = fminf(bv, fminf(d0, d1));
            }
            bv = fminf(bv, __shfl_xor_sync(0xffffffffu, bv, 1));
            bv = fminf(bv, __shfl_xor_sync(0xffffffffu, bv, 2));
            if ((lane & 3) == 0) wval[row * 8 + nw] = bv;
        }
    __syncthreads();
    if (tid < MROWS) {
        float m = wval[tid * 8];
        #pragma unroll
        for (int w = 1; w < 8; ++w) m = fminf(m, wval[tid * 8 + w]);
        rmin[tid] = m;
    }
    __syncthreads();

    // pass 2: append candidates within MARGIN of the screened min
    #pragma unroll
    for (int mt = 0; mt < 4; ++mt)
        #pragma unroll
        for (int h = 0; h < 2; ++h) {
            const int row = mt * 16 + r0 + h * 8;
            const float thr = rmin[row] + MARGIN;
            #pragma unroll
            for (int nt = 0; nt < 4; ++nt) {
                const int col = nw * 32 + nt * 8 + c0;
                const float d0 = csq_s[col]     - 2.0f * acc[mt][nt][2*h];
                const float d1 = csq_s[col + 1] - 2.0f * acc[mt][nt][2*h+1];
                if (d0 <= thr) {
                    const int p = atomicAdd(&cnt[row], 1);
                    if (p < NCAND) cand[row * NCAND + p] = col;
                }
                if (d1 <= thr) {
                    const int p = atomicAdd(&cnt[row], 1);
                    if (p < NCAND) cand[row * NCAND + p] = col + 1;
                }
            }
        }
    __syncthreads();

    // rescore: warp nw owns rows nw*8..nw*8+7; exact fp32 distance.
    // Overflow (cnt > NCAND) falls back to exact scan of all 256 codes.
    const float4* cb4 = (const float4*)cb;
    for (int rr = 0; rr < 8; ++rr) {
        const int row = nw * 8 + rr;
        const int n = cnt[row];
        int winner;
        if (n <= 1) {
            winner = (n == 1) ? cand[row * NCAND] : 0;
        } else {
            const bool full = (n > NCAND);
            const int m = full ? CODES : n;
            float4 xr[8];
            const float4* xp = (const float4*)(src + (size_t)row * H);
            #pragma unroll
            for (int t = 0; t < 8; ++t) xr[t] = __ldg(xp + lane + 32 * t);
            float best = 3.4e38f; int bi = CODES;
            for (int j = 0; j < m; ++j) {
                const int c = full ? j : cand[row * NCAND + j];
                float p = 0.f;
                #pragma unroll
                for (int t = 0; t < 8; ++t) {
                    const float4 cv = __ldg(cb4 + (size_t)c * (H / 4) + lane + 32 * t);
                    p += xr[t].x * cv.x + xr[t].y * cv.y
                       + xr[t].z * cv.z + xr[t].w * cv.w;
                }
                #pragma unroll
                for (int o = 16; o; o >>= 1) p += __shfl_xor_sync(0xffffffffu, p, o);
                const float d = csq_s[c] - 2.0f * p;
                if (d < best || (d == best && c < bi)) { best = d; bi = c; }
            }
            winner = bi;
        }
        if (lane == 0) idxs[row] = winner;
    }
    __syncthreads();

    // gather winning codebook rows, apply sparsity mask, write coalesced
    float4* o4 = (float4*)out + (size_t)bid * MROWS * (H / 4);
    for (int r = 0; r < MROWS; ++r) {
        const int idx = idxs[r];
        const float sc = (csq_s[idx] > 0.01f) ? 1.0f : 0.0f;   // ||c|| > 0.1
        float4 v = cb4[(size_t)idx * (H / 4) + tid];
        v.x *= sc; v.y *= sc; v.z *= sc; v.w *= sc;
        o4[(size_t)r * (H / 4) + tid] = v;
    }
}

// ---------------------------------------------------------------- launch
extern "C" void kernel_launch(void* const* d_in, const int* in_sizes, int n_in,
                              void* d_out, int out_size) {
    const float* keys     = (const float*)d_in[0];
    const float* values   = (const float*)d_in[1];
    const float* codebook = (const float*)d_in[2];
    float* out = (float*)d_out;
    (void)in_sizes; (void)n_in; (void)out_size;

    cudaFuncSetAttribute(vq_kernel, cudaFuncAttributeMaxDynamicSharedMemorySize, SMEM_TOTAL);
    csq_kernel<<<CODES, 256>>>(codebook);
    bprep_kernel<<<CODES, 256>>>(codebook);
    vq_kernel<<<512, 256, SMEM_TOTAL>>>(keys, values, codebook, out);
}